// round 17
// baseline (speedup 1.0000x reference)
#include <cuda_runtime.h>

#define NPTS    25600
#define XROW    407
#define NSTEPS  50
#define DTF     0.001f
#define NBLK    148
#define TPB     176       // 88 groups of 2 threads; each group = 2 points
#define NGRP    87        // active groups per block (148*87*2 = 25752 >= 25600)

typedef unsigned long long u64;

__device__ __forceinline__ u64 pk(float lo, float hi) {
    u64 r; asm("mov.b64 %0, {%1,%2};" : "=l"(r) : "f"(lo), "f"(hi)); return r;
}
__device__ __forceinline__ void upk(u64 v, float& lo, float& hi) {
    asm("mov.b64 {%0,%1}, %2;" : "=f"(lo), "=f"(hi) : "l"(v));
}
__device__ __forceinline__ float lo64(u64 v) { float a,b; upk(v,a,b); return a; }
__device__ __forceinline__ float hi64(u64 v) { float a,b; upk(v,a,b); return b; }
__device__ __forceinline__ u64 swap2(u64 v) { float a,b; upk(v,a,b); return pk(b,a); }
__device__ __forceinline__ u64 ffma2(u64 a, u64 b, u64 c) {
    u64 d; asm("fma.rn.f32x2 %0, %1, %2, %3;" : "=l"(d) : "l"(a), "l"(b), "l"(c)); return d;
}
__device__ __forceinline__ u64 fmul2(u64 a, u64 b) {
    u64 d; asm("mul.rn.f32x2 %0, %1, %2;" : "=l"(d) : "l"(a), "l"(b)); return d;
}
__device__ __forceinline__ u64 fadd2(u64 a, u64 b) {
    u64 d; asm("add.rn.f32x2 %0, %1, %2;" : "=l"(d) : "l"(a), "l"(b)); return d;
}
__device__ __forceinline__ float softplus_f(float z) {
    float e = __expf(-fabsf(z));
    return fmaxf(z, 0.0f) + __logf(1.0f + e);
}
__device__ __forceinline__ float sig_only(float z) {
    float e = __expf(-fabsf(z));
    float u = 1.0f + e;
    float r; asm("rcp.approx.f32 %0, %1;" : "=f"(r) : "f"(u));
    return (z >= 0.0f) ? r : e * r;
}
__device__ __forceinline__ float sig_from_h(float h) { return 1.0f - __expf(-h); }
__device__ __forceinline__ u64 softplus2(u64 z) {
    float a, b; upk(z, a, b); return pk(softplus_f(a), softplus_f(b));
}
__device__ __forceinline__ u64 sig2(u64 z) {
    float a, b; upk(z, a, b); return pk(sig_only(a), sig_only(b));
}
__device__ __forceinline__ u64 sig2h(u64 h) {
    float a, b; upk(h, a, b); return pk(sig_from_h(a), sig_from_h(b));
}
// unscramble cross-pack accumulators: A=(z_r0_pA, z_r1_pB), B=(z_r0_pB, z_r1_pA)
__device__ __forceinline__ u64 unsL(u64 A, u64 B) { return pk(lo64(A), lo64(B)); } // z_r0
__device__ __forceinline__ u64 unsH(u64 A, u64 B) { return pk(hi64(B), hi64(A)); } // z_r1

// ---------- smem layout (float offsets) ----------
// forward chunks: (w[r0][k0], w[r1][k0], w[r0][k0+1], w[r1][k0+1])
#define OFW1  0                      // w0: [h][t] t<4, r0=8h+2t:         32
#define OFW2  32                     // w1: [h][t<8][kp<8],  r0=16h+2t:  512
#define OFW3  (OFW2 + 512)           // w2: [h][t<8][kp<16], r0=16h+2t: 1024
#define OFW4  (OFW3 + 1024)          // w3: [h][t<4][kp<16], r0=8h+2t:   512
// backward: plain row-major
#define OBW3  (OFW4 + 512)           // w3 16x32:  512
#define OBW2  (OBW3 + 512)           // w2 32x32: 1024
#define OBW1  (OBW2 + 1024)          // w1 32x16:  512
#define OW0D  (OBW1 + 512)           // [c<16]: (w0[c][0]dup, w0[c][1]dup): 64
#define OW4D  (OW0D + 64)            // [r<16]: (w4[r], w4[r]): 32
#define OB0C  (OW4D + 32)            // [h][t<4]: (b0[r0], b0[r0+1]): 16
#define OB1C  (OB0C + 16)            // [h][t<8]: 32
#define OB2C  (OB1C + 32)            // 32
#define OB3C  (OB2C + 32)            // [h][t<4]: 16
#define OWT   (OB3C + 16)            // 4
#define SMEMF (OWT + 8)

__global__ void __launch_bounds__(TPB, 1)
phinn_kernel(const float* __restrict__ x,
             const float* __restrict__ w0, const float* __restrict__ b0,
             const float* __restrict__ w1, const float* __restrict__ b1,
             const float* __restrict__ w2, const float* __restrict__ b2,
             const float* __restrict__ w3, const float* __restrict__ b3,
             const float* __restrict__ w4,
             const float* __restrict__ wt,
             float* __restrict__ out)
{
    __shared__ __align__(128) float sm[SMEMF];
    const int tid = threadIdx.x;
    const int gid = tid >> 1;
    const int h   = tid & 1;
    const bool hb = (h != 0);

    // ---- stage weights ----
    for (int i = tid; i < 32; i += TPB) {           // w0 fwd
        int r = i >> 1, d = i & 1;
        int hh = r >> 3, j = r & 7, t = j >> 1, rr = j & 1;
        sm[OFW1 + (hh*4 + t)*4 + d*2 + rr] = w0[i];
    }
    for (int i = tid; i < 512; i += TPB) {          // w1 fwd
        int r = i >> 4, k = i & 15;
        int hh = r >> 4, j = r & 15, t = j >> 1, rr = j & 1;
        int kp = k >> 1, kr = k & 1;
        sm[OFW2 + ((hh*8 + t)*8 + kp)*4 + kr*2 + rr] = w1[i];
    }
    for (int i = tid; i < 1024; i += TPB) {         // w2 fwd
        int r = i >> 5, k = i & 31;
        int hh = r >> 4, j = r & 15, t = j >> 1, rr = j & 1;
        int kp = k >> 1, kr = k & 1;
        sm[OFW3 + ((hh*8 + t)*16 + kp)*4 + kr*2 + rr] = w2[i];
    }
    for (int i = tid; i < 512; i += TPB) {          // w3 fwd
        int r = i >> 5, k = i & 31;
        int hh = r >> 3, j = r & 7, t = j >> 1, rr = j & 1;
        int kp = k >> 1, kr = k & 1;
        sm[OFW4 + ((hh*4 + t)*16 + kp)*4 + kr*2 + rr] = w3[i];
    }
    for (int i = tid; i < 512; i += TPB)  sm[OBW3 + i] = w3[i];   // row-major 16x32
    for (int i = tid; i < 1024; i += TPB) sm[OBW2 + i] = w2[i];   // row-major 32x32
    for (int i = tid; i < 512; i += TPB)  sm[OBW1 + i] = w1[i];   // row-major 32x16
    if (tid < 16) {
        int c = tid;
        sm[OW0D + c*4 + 0] = w0[2*c];     sm[OW0D + c*4 + 1] = w0[2*c];
        sm[OW0D + c*4 + 2] = w0[2*c + 1]; sm[OW0D + c*4 + 3] = w0[2*c + 1];
        sm[OW4D + c*2] = w4[c]; sm[OW4D + c*2 + 1] = w4[c];
        int hh = c >> 3, j = c & 7;
        sm[OB0C + (hh*4 + (j >> 1))*2 + (j & 1)] = b0[c];
        sm[OB3C + (hh*4 + (j >> 1))*2 + (j & 1)] = b3[c];
    }
    if (tid < 32) {
        int r = tid;
        int hh = r >> 4, j = r & 15;
        sm[OB1C + (hh*8 + (j >> 1))*2 + (j & 1)] = b1[r];
        sm[OB2C + (hh*8 + (j >> 1))*2 + (j & 1)] = b2[r];
    }
    if (tid < 4) sm[OWT + tid] = wt[tid];
    __syncthreads();

    // ---- 2-point group assignment ----
    const int  gIdx   = blockIdx.x * NGRP + gid;
    const bool active = (gid < NGRP) && (gIdx < NPTS / 2);
    const int  g  = active ? gIdx : (NPTS / 2 - 1);
    const int  pA = 2 * g, pB = pA + 1;
    const int  bA = pA / 200, cA = pA - bA * 200;
    const int  bB = pB / 200, cB = pB - bB * 200;
    const float* xA = x + bA * XROW;
    const float* xB = x + bB * XROW;

    u64 y0p = pk(xA[2 + 2*cA], xB[2 + 2*cB]);
    u64 y1p = pk(xA[3 + 2*cA], xB[3 + 2*cB]);
    float tsA = xA[0], tsB = xB[0];
    const float spA = xA[402], spB = xB[402];
    const float wt0 = sm[OWT], wt1 = sm[OWT+1], wt2 = sm[OWT+2], wt3 = sm[OWT+3];
    const float tA0A = fmaf(xA[403], wt0, xA[404] * wt1);
    const float tA1A = fmaf(xA[403], wt2, xA[404] * wt3);
    const float tB0A = fmaf(xA[405], wt0, xA[406] * wt1);
    const float tB1A = fmaf(xA[405], wt2, xA[406] * wt3);
    const float tA0B = fmaf(xB[403], wt0, xB[404] * wt1);
    const float tA1B = fmaf(xB[403], wt2, xB[404] * wt3);
    const float tB0B = fmaf(xB[405], wt0, xB[406] * wt1);
    const float tB1B = fmaf(xB[405], wt2, xB[406] * wt3);
    const u64 NDT2 = pk(-DTF, -DTF);

    const float* __restrict__ smv = sm;

    // exchange: own[j] = row (n*h + j); vd gets natural order, constant indices
    #define XC(vd, own, n)                                                     \
        do {                                                                   \
            _Pragma("unroll")                                                  \
            for (int _j = 0; _j < (n); ++_j) {                                 \
                u64 _o = __shfl_xor_sync(0xffffffffu, (own)[_j], 1);           \
                (vd)[_j]       = hb ? _o : (own)[_j];                          \
                (vd)[(n) + _j] = hb ? (own)[_j] : _o;                          \
            }                                                                  \
        } while (0)

    u64 vd[32];
    u64 h1o[8], h2o[16], h3o[16];

    #pragma unroll 1
    for (int it = 0; it < NSTEPS; ++it) {
        const bool eA = (tsA < spA), eB = (tsB < spB);
        const u64 ti0 = pk(eA ? tA0A : tB0A, eB ? tA0B : tB0B);
        const u64 ti1 = pk(eA ? tA1A : tB1A, eB ? tA1B : tB1B);

        // ---- L1 (w0): own rows 8h+2t,+1 ----
        {
            u64 y0s = swap2(y0p), y1s = swap2(y1p);
            #pragma unroll
            for (int t = 0; t < 4; ++t) {
                ulonglong2 w = *(const ulonglong2*)(smv + OFW1 + (h*4 + t)*4);
                u64 bb = *(const u64*)(smv + OB0C + (h*4 + t)*2);
                u64 A = ffma2(w.x, y0p, bb);
                u64 B = ffma2(w.x, y0s, bb);
                A = ffma2(w.y, y1p, A);
                B = ffma2(w.y, y1s, B);
                h1o[2*t]     = softplus2(unsL(A, B));
                h1o[2*t + 1] = softplus2(unsH(A, B));
            }
        }
        XC(vd, h1o, 8);     // vd[0..15] = full h1

        // ---- L2 (w1, 16 k): own rows 16h+2t,+1, t<8 ----
        {
            u64 A[8], B[8];
            #pragma unroll
            for (int t = 0; t < 8; ++t) {
                u64 bb = *(const u64*)(smv + OB1C + (h*8 + t)*2);
                A[t] = bb; B[t] = bb;
            }
            #pragma unroll
            for (int kp = 0; kp < 8; ++kp) {
                u64 vk = vd[2*kp], vk1 = vd[2*kp + 1];
                u64 vks = swap2(vk), vk1s = swap2(vk1);
                #pragma unroll
                for (int t = 0; t < 8; ++t) {
                    ulonglong2 w = *(const ulonglong2*)(smv + OFW2 + ((h*8 + t)*8 + kp)*4);
                    A[t] = ffma2(w.x, vk,  A[t]);  B[t] = ffma2(w.x, vks,  B[t]);
                    A[t] = ffma2(w.y, vk1, A[t]);  B[t] = ffma2(w.y, vk1s, B[t]);
                }
            }
            #pragma unroll
            for (int t = 0; t < 8; ++t) {
                h2o[2*t]     = softplus2(unsL(A[t], B[t]));
                h2o[2*t + 1] = softplus2(unsH(A[t], B[t]));
            }
        }
        XC(vd, h2o, 16);    // full h2

        // ---- L3 (w2, 32 k): own rows 16h+2t,+1 ----
        {
            u64 A[8], B[8];
            #pragma unroll
            for (int t = 0; t < 8; ++t) {
                u64 bb = *(const u64*)(smv + OB2C + (h*8 + t)*2);
                A[t] = bb; B[t] = bb;
            }
            #pragma unroll
            for (int kp = 0; kp < 16; ++kp) {
                u64 vk = vd[2*kp], vk1 = vd[2*kp + 1];
                u64 vks = swap2(vk), vk1s = swap2(vk1);
                #pragma unroll
                for (int t = 0; t < 8; ++t) {
                    ulonglong2 w = *(const ulonglong2*)(smv + OFW3 + ((h*8 + t)*16 + kp)*4);
                    A[t] = ffma2(w.x, vk,  A[t]);  B[t] = ffma2(w.x, vks,  B[t]);
                    A[t] = ffma2(w.y, vk1, A[t]);  B[t] = ffma2(w.y, vk1s, B[t]);
                }
            }
            #pragma unroll
            for (int t = 0; t < 8; ++t) {
                h3o[2*t]     = softplus2(unsL(A[t], B[t]));
                h3o[2*t + 1] = softplus2(unsH(A[t], B[t]));
            }
        }
        XC(vd, h3o, 16);    // full h3

        // ---- L4 (w3, 32 k): own rows 8h+2t,+1, t<4; g4 = sig*w4 ----
        u64 g4o[8];
        {
            u64 A[4], B[4];
            #pragma unroll
            for (int t = 0; t < 4; ++t) {
                u64 bb = *(const u64*)(smv + OB3C + (h*4 + t)*2);
                A[t] = bb; B[t] = bb;
            }
            #pragma unroll
            for (int kp = 0; kp < 16; ++kp) {
                u64 vk = vd[2*kp], vk1 = vd[2*kp + 1];
                u64 vks = swap2(vk), vk1s = swap2(vk1);
                #pragma unroll
                for (int t = 0; t < 4; ++t) {
                    ulonglong2 w = *(const ulonglong2*)(smv + OFW4 + ((h*4 + t)*16 + kp)*4);
                    A[t] = ffma2(w.x, vk,  A[t]);  B[t] = ffma2(w.x, vks,  B[t]);
                    A[t] = ffma2(w.y, vk1, A[t]);  B[t] = ffma2(w.y, vk1s, B[t]);
                }
            }
            #pragma unroll
            for (int t = 0; t < 4; ++t) {
                int r0 = 8*h + 2*t;
                g4o[2*t]     = fmul2(sig2(unsL(A[t], B[t])), *(const u64*)(smv + OW4D + r0*2));
                g4o[2*t + 1] = fmul2(sig2(unsH(A[t], B[t])), *(const u64*)(smv + OW4D + (r0 + 1)*2));
            }
        }
        XC(vd, g4o, 8);     // vd[0..15] = full g4

        // ---- g3 (w3 bwd): own cols 16h+0..15 ----
        u64 g3o[16];
        {
            u64 aA[8], aB[8];
            #pragma unroll
            for (int j = 0; j < 8; ++j) { aA[j] = 0ULL; aB[j] = 0ULL; }
            #pragma unroll
            for (int r = 0; r < 16; ++r) {
                u64 gr = vd[r], grs = swap2(gr);
                #pragma unroll
                for (int u = 0; u < 4; ++u) {
                    ulonglong2 w = *(const ulonglong2*)(smv + OBW3 + r*32 + 16*h + 4*u);
                    aA[2*u]     = ffma2(w.x, gr,  aA[2*u]);
                    aB[2*u]     = ffma2(w.x, grs, aB[2*u]);
                    aA[2*u + 1] = ffma2(w.y, gr,  aA[2*u + 1]);
                    aB[2*u + 1] = ffma2(w.y, grs, aB[2*u + 1]);
                }
            }
            #pragma unroll
            for (int cp = 0; cp < 8; ++cp) {
                g3o[2*cp]     = fmul2(unsL(aA[cp], aB[cp]), sig2h(h3o[2*cp]));
                g3o[2*cp + 1] = fmul2(unsH(aA[cp], aB[cp]), sig2h(h3o[2*cp + 1]));
            }
        }
        XC(vd, g3o, 16);    // full g3

        // ---- g2 (w2 bwd): own cols 16h+0..15 ----
        u64 g2o[16];
        {
            u64 aA[8], aB[8];
            #pragma unroll
            for (int j = 0; j < 8; ++j) { aA[j] = 0ULL; aB[j] = 0ULL; }
            #pragma unroll
            for (int r = 0; r < 32; ++r) {
                u64 gr = vd[r], grs = swap2(gr);
                #pragma unroll
                for (int u = 0; u < 4; ++u) {
                    ulonglong2 w = *(const ulonglong2*)(smv + OBW2 + r*32 + 16*h + 4*u);
                    aA[2*u]     = ffma2(w.x, gr,  aA[2*u]);
                    aB[2*u]     = ffma2(w.x, grs, aB[2*u]);
                    aA[2*u + 1] = ffma2(w.y, gr,  aA[2*u + 1]);
                    aB[2*u + 1] = ffma2(w.y, grs, aB[2*u + 1]);
                }
            }
            #pragma unroll
            for (int cp = 0; cp < 8; ++cp) {
                g2o[2*cp]     = fmul2(unsL(aA[cp], aB[cp]), sig2h(h2o[2*cp]));
                g2o[2*cp + 1] = fmul2(unsH(aA[cp], aB[cp]), sig2h(h2o[2*cp + 1]));
            }
        }
        XC(vd, g2o, 16);    // full g2

        // ---- g1 (w1 bwd): own cols 8h+0..7; gy ----
        u64 gy0p = 0ULL, gy1p = 0ULL;
        {
            u64 aA[4], aB[4];
            #pragma unroll
            for (int j = 0; j < 4; ++j) { aA[j] = 0ULL; aB[j] = 0ULL; }
            #pragma unroll
            for (int r = 0; r < 32; ++r) {
                u64 gr = vd[r], grs = swap2(gr);
                #pragma unroll
                for (int u = 0; u < 2; ++u) {
                    ulonglong2 w = *(const ulonglong2*)(smv + OBW1 + r*16 + 8*h + 4*u);
                    aA[2*u]     = ffma2(w.x, gr,  aA[2*u]);
                    aB[2*u]     = ffma2(w.x, grs, aB[2*u]);
                    aA[2*u + 1] = ffma2(w.y, gr,  aA[2*u + 1]);
                    aB[2*u + 1] = ffma2(w.y, grs, aB[2*u + 1]);
                }
            }
            #pragma unroll
            for (int cp = 0; cp < 4; ++cp) {
                int c0 = 8*h + 2*cp;
                u64 g1_0 = fmul2(unsL(aA[cp], aB[cp]), sig2h(h1o[2*cp]));
                u64 g1_1 = fmul2(unsH(aA[cp], aB[cp]), sig2h(h1o[2*cp + 1]));
                ulonglong2 w0c = *(const ulonglong2*)(smv + OW0D + c0*4);
                gy0p = ffma2(w0c.x, g1_0, gy0p);
                gy1p = ffma2(w0c.y, g1_0, gy1p);
                ulonglong2 w1c = *(const ulonglong2*)(smv + OW0D + (c0 + 1)*4);
                gy0p = ffma2(w1c.x, g1_1, gy0p);
                gy1p = ffma2(w1c.y, g1_1, gy1p);
            }
        }
        gy0p = fadd2(gy0p, __shfl_xor_sync(0xffffffffu, gy0p, 1));
        gy1p = fadd2(gy1p, __shfl_xor_sync(0xffffffffu, gy1p, 1));

        y0p = ffma2(fadd2(gy0p, ti0), NDT2, y0p);
        y1p = ffma2(fadd2(gy1p, ti1), NDT2, y1p);
        tsA += DTF; tsB += DTF;
    }

    if (active) {
        if (!hb) { out[2*pA] = lo64(y0p); out[2*pA + 1] = lo64(y1p); }
        else     { out[2*pB] = hi64(y0p); out[2*pB + 1] = hi64(y1p); }
    }
}

extern "C" void kernel_launch(void* const* d_in, const int* in_sizes, int n_in,
                              void* d_out, int out_size)
{
    int xi = -1;
    for (int i = 0; i < n_in; ++i)
        if (in_sizes[i] == 128 * XROW) { xi = i; break; }

    const float *x, *W[5], *B[5], *wtp;
    if (xi == 0) {
        x = (const float*)d_in[0];
        for (int i = 0; i < 5; ++i) {
            W[i] = (const float*)d_in[1 + 2 * i];
            B[i] = (const float*)d_in[2 + 2 * i];
        }
        wtp = (const float*)d_in[11];
    } else {
        for (int i = 0; i < 5; ++i) {
            W[i] = (const float*)d_in[2 * i];
            B[i] = (const float*)d_in[2 * i + 1];
        }
        wtp = (const float*)d_in[10];
        x   = (const float*)d_in[(xi >= 0) ? xi : 11];
    }

    float* out = (float*)d_out;
    phinn_kernel<<<NBLK, TPB>>>(x,
                                W[0], B[0], W[1], B[1], W[2], B[2],
                                W[3], B[3], W[4], wtp, out);
}